// round 4
// baseline (speedup 1.0000x reference)
#include <cuda_runtime.h>
#include <stdint.h>

// ============================================================================
// MMD loss via tensor-core mma.sync (tf32), family-portable PTX (sm_103 base).
//   sum(L2) = 2*M*sum||x_i||^2 - 2*||sum x_i||^2  (M=8192)
//   bw = sum(L2)/(M^2-M)/4 ; e = exp(-L2/(16 bw))
//   kernel sum = e + e^2 + e^4 + e^8 + e^16 ; loss = -2*mean(cross block)
//
// R4: warp tile 64x64 (4 warps/CTA, 3 CTAs/SM), coalesced smem-staged permute.
// ============================================================================

#define NROWS 4096
#define D     256
#define M_TOT 8192

__device__ float g_sq[M_TOT];
__device__ float g_colsum_part[64][256];
__device__ float g_inv_b16;
__device__ float g_part[1024];
__device__ int   g_ctr1;
__device__ int   g_ctr2;
__device__ float g_Aperm[NROWS * D];   // [tile_m(256)][tk(32)][lane(32)][4]
__device__ float g_Bperm[NROWS * D];   // [pair(256)][tk(32)][lane(32)][4]

// ---------------------------------------------------------------------------
__device__ __forceinline__ uint32_t smem_u32(const void* p) {
    uint32_t a;
    asm("{ .reg .u64 t; cvta.to.shared.u64 t, %1; cvt.u32.u64 %0, t; }"
        : "=r"(a) : "l"(p));
    return a;
}
__device__ __forceinline__ void cp_async16(uint32_t s, const void* g) {
    asm volatile("cp.async.cg.shared.global [%0], [%1], 16;"
                 :: "r"(s), "l"(g) : "memory");
}
#define CP_COMMIT() asm volatile("cp.async.commit_group;" ::: "memory")
#define CP_WAIT(n)  asm volatile("cp.async.wait_group %0;" :: "n"(n) : "memory")

__device__ __forceinline__ void mma_tf32(float* c, uint32_t a0, uint32_t a1,
                                         uint32_t a2, uint32_t a3,
                                         uint32_t b0, uint32_t b1) {
    asm volatile(
        "mma.sync.aligned.m16n8k8.row.col.f32.tf32.tf32.f32 "
        "{%0,%1,%2,%3}, {%4,%5,%6,%7}, {%8,%9}, {%0,%1,%2,%3};"
        : "+f"(c[0]), "+f"(c[1]), "+f"(c[2]), "+f"(c[3])
        : "r"(a0), "r"(a1), "r"(a2), "r"(a3), "r"(b0), "r"(b1));
}

__device__ __forceinline__ const float* row_ptr(const float* s, const float* t, int r) {
    return (r < NROWS) ? (s + (size_t)r * D) : (t + (size_t)(r - NROWS) * D);
}

// ---------------------------------------------------------------------------
// Kernel 1: stats (colsum partials, row norms, bandwidth tail) + coalesced
// fragment permute via padded smem tiles. 64 blocks x 256 threads.
// ---------------------------------------------------------------------------
__global__ __launch_bounds__(256) void stats_kernel(const float* __restrict__ src,
                                                    const float* __restrict__ tgt) {
    const int blk = blockIdx.x, tid = threadIdx.x;
    const int base = blk * 128;
    const int w = tid >> 5, lane = tid & 31;

    // column-sum partials (coalesced)
    float s = 0.f;
    for (int r = 0; r < 128; r++) s += row_ptr(src, tgt, base + r)[tid];
    g_colsum_part[blk][tid] = s;

    // row squared norms (coalesced float4, warp per 16 rows)
    for (int r = 0; r < 16; r++) {
        const int row = base + w * 16 + r;
        const float4* p4 = (const float4*)row_ptr(src, tgt, row);
        float4 a = p4[lane], b = p4[lane + 32];
        float sq = a.x*a.x + a.y*a.y + a.z*a.z + a.w*a.w
                 + b.x*b.x + b.y*b.y + b.z*b.z + b.w*b.w;
        #pragma unroll
        for (int off = 16; off > 0; off >>= 1) sq += __shfl_xor_sync(0xffffffffu, sq, off);
        if (lane == 0) g_sq[row] = sq;
    }

    // coalesced fragment permute through padded smem (16 rows per group)
    __shared__ float tile[16][260];   // pad 4 floats: bank = (4g+t+8tk)%32, conflict-free
    const bool isA = (blk < 32);
    const float* sbase = isA ? (src + (size_t)base * D)
                             : (tgt + (size_t)(base - NROWS) * D);
    for (int grp = 0; grp < 8; grp++) {
        __syncthreads();
        const float* rp = sbase + (size_t)grp * 16 * D;
        #pragma unroll
        for (int i = tid; i < 1024; i += 256) {
            const int r = i >> 6, c4 = (i & 63) * 4;
            float4 v = *(const float4*)(rp + (size_t)r * D + c4);
            tile[r][c4] = v.x; tile[r][c4 + 1] = v.y;
            tile[r][c4 + 2] = v.z; tile[r][c4 + 3] = v.w;
        }
        __syncthreads();
        const int tidx = (isA ? blk * 8 : (blk - 32) * 8) + grp;
        float4* dst = (isA ? (float4*)g_Aperm : (float4*)g_Bperm) + (size_t)tidx * 1024;
        #pragma unroll
        for (int i = tid; i < 1024; i += 256) {
            const int tk = i >> 5, l = i & 31, gg = l >> 2, tt = l & 3;
            float4 v;
            if (isA) {   // A frag: a0=(g,t) a1=(g+8,t) a2=(g,t+4) a3=(g+8,t+4)
                v.x = tile[gg][tk * 8 + tt];     v.y = tile[gg + 8][tk * 8 + tt];
                v.z = tile[gg][tk * 8 + tt + 4]; v.w = tile[gg + 8][tk * 8 + tt + 4];
            } else {     // B frags, 2 n-tiles packed: (g,t),(g,t+4) | (g+8,t),(g+8,t+4)
                v.x = tile[gg][tk * 8 + tt];     v.y = tile[gg][tk * 8 + tt + 4];
                v.z = tile[gg + 8][tk * 8 + tt]; v.w = tile[gg + 8][tk * 8 + tt + 4];
            }
            dst[i] = v;   // contiguous 16B per thread -> fully coalesced
        }
    }

    // last-block tail: bandwidth
    __shared__ int is_last;
    __threadfence();
    if (tid == 0) is_last = (atomicAdd(&g_ctr1, 1) == 63);
    __syncthreads();
    if (!is_last) return;
    __threadfence();

    __shared__ double r1[256], r2[256];
    float cs = 0.f;
    #pragma unroll 8
    for (int p = 0; p < 64; p++) cs += g_colsum_part[p][tid];
    double ssq = (double)cs * (double)cs;
    double sumsq = 0.0;
    #pragma unroll 8
    for (int m = 0; m < M_TOT / 256; m++) sumsq += (double)g_sq[tid + m * 256];
    r1[tid] = ssq; r2[tid] = sumsq;
    __syncthreads();
    for (int st = 128; st > 0; st >>= 1) {
        if (tid < st) { r1[tid] += r1[tid + st]; r2[tid] += r2[tid + st]; }
        __syncthreads();
    }
    if (tid == 0) {
        const double M = (double)M_TOT;
        double sumL2 = 2.0 * M * r2[0] - 2.0 * r1[0];
        double bw = sumL2 / (M * M - M) / 4.0;
        g_inv_b16 = (float)(1.0 / (bw * 16.0));
        g_ctr1 = 0;   // reset for graph replay
    }
}

// ---------------------------------------------------------------------------
// Kernel 2: tf32 mma GEMM + fused exp epilogue. 1024 CTAs x 128 threads.
// CTA tile 128x128, 4 warps of 64x64, k-chunks of 32, 2-stage cp.async.
// ---------------------------------------------------------------------------
#define OPND_BYTES 16384
#define BUF_BYTES  32768
#define SMEM_TJ    (2 * BUF_BYTES)
#define SMEM_RED   (SMEM_TJ + 512)
#define SMEM_TOT   (SMEM_RED + 64)

__global__ __launch_bounds__(128, 3)
void mmd_mma_kernel(float* __restrict__ out) {
    extern __shared__ char smem[];
    const uint32_t sb = smem_u32(smem);
    const int tid = threadIdx.x, wid = tid >> 5, lane = tid & 31;
    const int g = lane >> 2, t = lane & 3;
    const int warp_m = wid & 1, warp_n = wid >> 1;
    const int bx = blockIdx.x, by = blockIdx.y;

    float* tjs = (float*)(smem + SMEM_TJ);
    tjs[tid] = g_sq[NROWS + bx * 128 + tid];

    float acc[4][8][4];
    #pragma unroll
    for (int i = 0; i < 4; i++)
        #pragma unroll
        for (int j = 0; j < 8; j++)
            #pragma unroll
            for (int k = 0; k < 4; k++) acc[i][j][k] = 0.f;

    auto stage = [&](int kc, int buf) {
        const uint32_t sbuf = sb + buf * BUF_BYTES;
        #pragma unroll
        for (int v = 0; v < 8; v++) {
            const int soff = v * 2048 + tid * 16;
            const int seg = soff >> 9, within = soff & 511;
            const size_t ga = ((((size_t)(by * 8 + (seg >> 2)) * 32) + kc * 4 + (seg & 3)) << 9) + within;
            cp_async16(sbuf + soff, (const char*)g_Aperm + ga);
            const size_t gb = ((((size_t)(bx * 8 + (seg >> 2)) * 32) + kc * 4 + (seg & 3)) << 9) + within;
            cp_async16(sbuf + OPND_BYTES + soff, (const char*)g_Bperm + gb);
        }
    };

    stage(0, 0);
    CP_COMMIT();

    #pragma unroll 2
    for (int kc = 0; kc < 8; kc++) {
        if (kc < 7) {
            stage(kc + 1, (kc + 1) & 1);
            CP_COMMIT();
            CP_WAIT(1);
        } else {
            CP_WAIT(0);
        }
        __syncthreads();

        const uint4* As = (const uint4*)(smem + (kc & 1) * BUF_BYTES);
        const uint4* Bs = (const uint4*)(smem + (kc & 1) * BUF_BYTES + OPND_BYTES);

        #pragma unroll
        for (int ks = 0; ks < 4; ks++) {
            uint4 a[4];
            #pragma unroll
            for (int mt = 0; mt < 4; mt++)
                a[mt] = As[((warp_m * 4 + mt) * 4 + ks) * 32 + lane];
            #pragma unroll
            for (int pp = 0; pp < 4; pp++) {
                const uint4 b = Bs[((warp_n * 4 + pp) * 4 + ks) * 32 + lane];
                #pragma unroll
                for (int mt = 0; mt < 4; mt++) {
                    mma_tf32(acc[mt][2 * pp],     a[mt].x, a[mt].y, a[mt].z, a[mt].w, b.x, b.y);
                    mma_tf32(acc[mt][2 * pp + 1], a[mt].x, a[mt].y, a[mt].z, a[mt].w, b.z, b.w);
                }
            }
        }
        __syncthreads();
    }

    // epilogue: L2 -> 5-kernel exp sum
    const float inv_b16 = g_inv_b16;
    float si[4][2];
    #pragma unroll
    for (int mt = 0; mt < 4; mt++) {
        const int r0 = by * 128 + warp_m * 64 + mt * 16 + g;
        si[mt][0] = g_sq[r0];
        si[mt][1] = g_sq[r0 + 8];
    }

    float ksum = 0.f;
    #pragma unroll
    for (int nt = 0; nt < 8; nt++) {
        const int c0 = warp_n * 64 + nt * 8 + 2 * t;
        const float tj0 = tjs[c0], tj1 = tjs[c0 + 1];
        #pragma unroll
        for (int mt = 0; mt < 4; mt++) {
            const float* c = acc[mt][nt];
            #pragma unroll
            for (int q = 0; q < 4; q++) {
                const float L2 = si[mt][q >> 1] + ((q & 1) ? tj1 : tj0) - 2.f * c[q];
                const float e = __expf(-L2 * inv_b16);
                const float e2 = e * e, e4 = e2 * e2, e8 = e4 * e4;
                ksum += e + e2 + e4 + e8 + e8 * e8;
            }
        }
    }

    #pragma unroll
    for (int off = 16; off > 0; off >>= 1) ksum += __shfl_xor_sync(0xffffffffu, ksum, off);
    float* red = (float*)(smem + SMEM_RED);
    if (lane == 0) red[wid] = ksum;
    __syncthreads();
    if (tid == 0) g_part[by * 32 + bx] = red[0] + red[1] + red[2] + red[3];

    // last-CTA tail: final loss
    __shared__ int is_last;
    __threadfence();
    if (tid == 0) is_last = (atomicAdd(&g_ctr2, 1) == 1023);
    __syncthreads();
    if (!is_last) return;
    __threadfence();

    double sacc = 0.0;
    #pragma unroll
    for (int m = 0; m < 8; m++) sacc += (double)g_part[tid + m * 128];
    __shared__ double dred[128];
    dred[tid] = sacc;
    __syncthreads();
    for (int st = 64; st > 0; st >>= 1) {
        if (tid < st) dred[tid] += dred[tid + st];
        __syncthreads();
    }
    if (tid == 0) {
        double mean = dred[0] / ((double)NROWS * (double)NROWS);
        out[0] = (float)(-2.0 * mean);
        g_ctr2 = 0;   // reset for graph replay
    }
}

// ---------------------------------------------------------------------------
extern "C" void kernel_launch(void* const* d_in, const int* in_sizes, int n_in,
                              void* d_out, int out_size) {
    (void)in_sizes; (void)n_in; (void)out_size;
    const float* src = (const float*)d_in[0];
    const float* tgt = (const float*)d_in[1];
    float* out = (float*)d_out;

    cudaFuncSetAttribute(mmd_mma_kernel, cudaFuncAttributeMaxDynamicSharedMemorySize,
                         SMEM_TOT);

    stats_kernel<<<64, 256>>>(src, tgt);
    mmd_mma_kernel<<<dim3(32, 32), 128, SMEM_TOT>>>(out);
}

// round 5
// speedup vs baseline: 1.5825x; 1.5825x over previous
#include <cuda_runtime.h>
#include <cuda_bf16.h>
#include <stdint.h>

// ============================================================================
// MMD loss via mma.sync m16n8k16 bf16 (family-portable PTX; sm_103 base target).
//   sum(L2) = 2*M*sum||x_i||^2 - 2*||sum x_i||^2  (M=8192)
//   bw = sum(L2)/(M^2-M)/4 ; e = exp(-L2/(16 bw))
//   kernel sum = e + e^2 + e^4 + e^8 + e^16 ; loss = -2*mean(cross block)
// Norms in fp32; only the gram cross-term goes through bf16 tensor cores.
// R5: bf16 k16 HMMA (half the instructions/bytes of tf32 k8), 8-warp CTA
// (R3 shape), 3-stage cp.async pipeline, restructured single-pass stats.
// ============================================================================

#define NROWS 4096
#define D     256
#define M_TOT 8192

__device__ float    g_sq[M_TOT];
__device__ float    g_colsum_part[256][256];
__device__ float    g_inv_b16;
__device__ float    g_part[1024];
__device__ int      g_ctr1;
__device__ int      g_ctr2;
// bf16x2 fragment-major operands: [tile(256)][tk16(16)][lane(32)][4 regs]
__device__ uint32_t g_Aperm[NROWS * D / 2];
__device__ uint32_t g_Bperm[NROWS * D / 2];

// ---------------------------------------------------------------------------
__device__ __forceinline__ uint32_t smem_u32(const void* p) {
    uint32_t a;
    asm("{ .reg .u64 t; cvta.to.shared.u64 t, %1; cvt.u32.u64 %0, t; }"
        : "=r"(a) : "l"(p));
    return a;
}
__device__ __forceinline__ void cp_async16(uint32_t s, const void* g) {
    asm volatile("cp.async.cg.shared.global [%0], [%1], 16;"
                 :: "r"(s), "l"(g) : "memory");
}
#define CP_COMMIT() asm volatile("cp.async.commit_group;" ::: "memory")
#define CP_WAIT(n)  asm volatile("cp.async.wait_group %0;" :: "n"(n) : "memory")

// pack two fp32 -> bf16x2 (lo in low half)
__device__ __forceinline__ uint32_t pack_bf16x2(float lo, float hi) {
    uint32_t r;
    asm("cvt.rn.bf16x2.f32 %0, %1, %2;" : "=r"(r) : "f"(hi), "f"(lo));
    return r;
}

// m16n8k16 bf16 mma: D += A(16x16 row) * B(16x8 col)
__device__ __forceinline__ void mma_bf16(float* c, uint32_t a0, uint32_t a1,
                                         uint32_t a2, uint32_t a3,
                                         uint32_t b0, uint32_t b1) {
    asm volatile(
        "mma.sync.aligned.m16n8k16.row.col.f32.bf16.bf16.f32 "
        "{%0,%1,%2,%3}, {%4,%5,%6,%7}, {%8,%9}, {%0,%1,%2,%3};"
        : "+f"(c[0]), "+f"(c[1]), "+f"(c[2]), "+f"(c[3])
        : "r"(a0), "r"(a1), "r"(a2), "r"(a3), "r"(b0), "r"(b1));
}

// ---------------------------------------------------------------------------
// Kernel 1: stats + bf16 fragment permute, single gmem pass through smem.
// 256 blocks x 256 threads; block handles 32 rows of [src; tgt].
// ---------------------------------------------------------------------------
__global__ __launch_bounds__(256) void stats_kernel(const float* __restrict__ src,
                                                    const float* __restrict__ tgt) {
    const int blk = blockIdx.x, tid = threadIdx.x;
    const int w = tid >> 5, lane = tid & 31;
    const bool isA = (blk < 128);
    const int base = isA ? blk * 32 : (blk - 128) * 32;   // row base within src/tgt
    const float* sbase = (isA ? src : tgt) + (size_t)base * D;

    __shared__ float tile[32][260];   // pad: conflict-free for all access patterns

    // stage 32 rows x 256 cols (single gmem read of this slice)
    #pragma unroll
    for (int i = tid; i < 2048; i += 256) {
        const int r = i >> 6, c4 = (i & 63) * 4;
        float4 v = *(const float4*)(sbase + (size_t)r * D + c4);
        tile[r][c4] = v.x; tile[r][c4 + 1] = v.y;
        tile[r][c4 + 2] = v.z; tile[r][c4 + 3] = v.w;
    }
    __syncthreads();

    // column-sum partials (thread = column)
    float cs = 0.f;
    #pragma unroll 8
    for (int r = 0; r < 32; r++) cs += tile[r][tid];
    g_colsum_part[blk][tid] = cs;

    // row norms: warp w handles rows 4w..4w+3
    #pragma unroll
    for (int rr = 0; rr < 4; rr++) {
        const int r = w * 4 + rr;
        float sq = 0.f;
        #pragma unroll
        for (int j = 0; j < 8; j++) {
            const float x = tile[r][lane + 32 * j];
            sq += x * x;
        }
        #pragma unroll
        for (int off = 16; off > 0; off >>= 1) sq += __shfl_xor_sync(0xffffffffu, sq, off);
        if (lane == 0) g_sq[(isA ? base : NROWS + base) + r] = sq;
    }

    // fragment permute (2 subtiles x 16 tk x 32 lanes = 1024 uint4 items)
    const int tile0 = (isA ? blk : blk - 128) * 2;
    uint4* dst = (uint4*)(isA ? g_Aperm : g_Bperm);
    #pragma unroll
    for (int i = tid; i < 1024; i += 256) {
        const int sub = i >> 9, tk = (i >> 5) & 15, l = i & 31;
        const int g = l >> 2, t = l & 3;
        const int r0 = sub * 16 + g, r1 = r0 + 8, c = tk * 16 + 2 * t;
        uint4 v;
        if (isA) {  // A: a0=(g,2t:2t+1) a1=(g+8,·) a2=(g,2t+8:2t+9) a3=(g+8,·)
            v.x = pack_bf16x2(tile[r0][c],     tile[r0][c + 1]);
            v.y = pack_bf16x2(tile[r1][c],     tile[r1][c + 1]);
            v.z = pack_bf16x2(tile[r0][c + 8], tile[r0][c + 9]);
            v.w = pack_bf16x2(tile[r1][c + 8], tile[r1][c + 9]);
        } else {    // B: two n-tiles packed: (b0,b1) of tile 2p | (b0,b1) of 2p+1
            v.x = pack_bf16x2(tile[r0][c],     tile[r0][c + 1]);
            v.y = pack_bf16x2(tile[r0][c + 8], tile[r0][c + 9]);
            v.z = pack_bf16x2(tile[r1][c],     tile[r1][c + 1]);
            v.w = pack_bf16x2(tile[r1][c + 8], tile[r1][c + 9]);
        }
        dst[(size_t)(tile0 + sub) * 512 + (tk * 32 + l)] = v;
    }

    // last-block tail: bandwidth
    __shared__ int is_last;
    __threadfence();
    if (tid == 0) is_last = (atomicAdd(&g_ctr1, 1) == 255);
    __syncthreads();
    if (!is_last) return;
    __threadfence();

    __shared__ double r1s[256], r2s[256];
    float csum = 0.f;
    #pragma unroll 16
    for (int p = 0; p < 256; p++) csum += g_colsum_part[p][tid];
    double ssq = (double)csum * (double)csum;
    double sumsq = 0.0;
    #pragma unroll 8
    for (int m = 0; m < M_TOT / 256; m++) sumsq += (double)g_sq[tid + m * 256];
    r1s[tid] = ssq; r2s[tid] = sumsq;
    __syncthreads();
    for (int st = 128; st > 0; st >>= 1) {
        if (tid < st) { r1s[tid] += r1s[tid + st]; r2s[tid] += r2s[tid + st]; }
        __syncthreads();
    }
    if (tid == 0) {
        const double M = (double)M_TOT;
        double sumL2 = 2.0 * M * r2s[0] - 2.0 * r1s[0];
        double bw = sumL2 / (M * M - M) / 4.0;
        g_inv_b16 = (float)(1.0 / (bw * 16.0));
        g_ctr1 = 0;   // reset for graph replay
    }
}

// ---------------------------------------------------------------------------
// Kernel 2: bf16 mma GEMM + fused exp epilogue. 1024 CTAs x 256 threads.
// CTA 128x128, warp 32x64 (8 warps), k-chunks of 32, 3-stage cp.async.
// ---------------------------------------------------------------------------
#define OPND_BYTES 8192                       // 128 x 32 bf16
#define BUF_BYTES  16384
#define NSTAGE     3
#define SMEM_TJ    (NSTAGE * BUF_BYTES)       // 49152
#define SMEM_RED   (SMEM_TJ + 512)
#define SMEM_TOT   (SMEM_RED + 64)

__global__ __launch_bounds__(256, 2)
void mmd_mma_kernel(float* __restrict__ out) {
    extern __shared__ char smem[];
    const uint32_t sb = smem_u32(smem);
    const int tid = threadIdx.x, wid = tid >> 5, lane = tid & 31;
    const int g = lane >> 2, t = lane & 3;
    const int warp_m = wid & 3, warp_n = wid >> 2;
    const int bx = blockIdx.x, by = blockIdx.y;

    float* tjs = (float*)(smem + SMEM_TJ);
    if (tid < 128) tjs[tid] = g_sq[NROWS + bx * 128 + tid];

    float acc[2][8][4];
    #pragma unroll
    for (int i = 0; i < 2; i++)
        #pragma unroll
        for (int j = 0; j < 8; j++)
            #pragma unroll
            for (int k = 0; k < 4; k++) acc[i][j][k] = 0.f;

    // stage one 32-k chunk: A,B each 16 fragment-blocks of 512B
    auto stage = [&](int kc, int buf) {
        const uint32_t sbuf = sb + buf * BUF_BYTES;
        #pragma unroll
        for (int v = 0; v < 2; v++) {
            const int soff = v * 4096 + tid * 16;
            const int seg = soff >> 9, within = soff & 511;   // seg: blk 0..15
            const size_t ga = (((size_t)(by * 8 + (seg >> 1)) * 16 + kc * 2 + (seg & 1)) << 9) + within;
            cp_async16(sbuf + soff, (const char*)g_Aperm + ga);
            const size_t gb = (((size_t)(bx * 8 + (seg >> 1)) * 16 + kc * 2 + (seg & 1)) << 9) + within;
            cp_async16(sbuf + OPND_BYTES + soff, (const char*)g_Bperm + gb);
        }
    };

    stage(0, 0); CP_COMMIT();
    stage(1, 1); CP_COMMIT();

    int buf = 0;
    #pragma unroll
    for (int kc = 0; kc < 8; kc++) {
        if (kc < 6)      { stage(kc + 2, (kc + 2) % NSTAGE); CP_COMMIT(); CP_WAIT(2); }
        else if (kc == 6) CP_WAIT(1);
        else              CP_WAIT(0);
        __syncthreads();

        const uint4* As = (const uint4*)(smem + buf * BUF_BYTES);
        const uint4* Bs = (const uint4*)(smem + buf * BUF_BYTES + OPND_BYTES);

        #pragma unroll
        for (int ks = 0; ks < 2; ks++) {   // two k16 steps per 32-chunk
            uint4 a[2], b[4];
            #pragma unroll
            for (int mt = 0; mt < 2; mt++)
                a[mt] = As[((warp_m * 2 + mt) * 2 + ks) * 32 + lane];
            #pragma unroll
            for (int pp = 0; pp < 4; pp++)
                b[pp] = Bs[((warp_n * 4 + pp) * 2 + ks) * 32 + lane];
            #pragma unroll
            for (int mt = 0; mt < 2; mt++)
                #pragma unroll
                for (int pp = 0; pp < 4; pp++) {
                    mma_bf16(acc[mt][2 * pp],     a[mt].x, a[mt].y, a[mt].z, a[mt].w, b[pp].x, b[pp].y);
                    mma_bf16(acc[mt][2 * pp + 1], a[mt].x, a[mt].y, a[mt].z, a[mt].w, b[pp].z, b[pp].w);
                }
        }
        __syncthreads();
        if (++buf == NSTAGE) buf = 0;
    }

    // epilogue: L2 -> 5-kernel exp sum
    const float inv_b16 = g_inv_b16;
    float si[2][2];
    #pragma unroll
    for (int mt = 0; mt < 2; mt++) {
        const int r0 = by * 128 + warp_m * 32 + mt * 16 + g;
        si[mt][0] = g_sq[r0];
        si[mt][1] = g_sq[r0 + 8];
    }

    float ksum = 0.f;
    #pragma unroll
    for (int nt = 0; nt < 8; nt++) {
        const int c0 = warp_n * 64 + nt * 8 + 2 * t;
        const float tj0 = tjs[c0], tj1 = tjs[c0 + 1];
        #pragma unroll
        for (int mt = 0; mt < 2; mt++) {
            const float* c = acc[mt][nt];
            #pragma unroll
            for (int q = 0; q < 4; q++) {
                const float L2 = si[mt][q >> 1] + ((q & 1) ? tj1 : tj0) - 2.f * c[q];
                const float e = __expf(-L2 * inv_b16);
                const float e2 = e * e, e4 = e2 * e2, e8 = e4 * e4;
                ksum += e + e2 + e4 + e8 + e8 * e8;
            }
        }
    }

    #pragma unroll
    for (int off = 16; off > 0; off >>= 1) ksum += __shfl_xor_sync(0xffffffffu, ksum, off);
    float* red = (float*)(smem + SMEM_RED);
    if (lane == 0) red[wid] = ksum;
    __syncthreads();
    if (tid == 0) {
        float bsum = 0.f;
        #pragma unroll
        for (int i = 0; i < 8; i++) bsum += red[i];
        g_part[by * 32 + bx] = bsum;
    }

    // last-CTA tail: final loss
    __shared__ int is_last;
    __threadfence();
    if (tid == 0) is_last = (atomicAdd(&g_ctr2, 1) == 1023);
    __syncthreads();
    if (!is_last) return;
    __threadfence();

    double sacc = 0.0;
    #pragma unroll
    for (int m = 0; m < 4; m++) sacc += (double)g_part[tid + m * 256];
    __shared__ double dred[256];
    dred[tid] = sacc;
    __syncthreads();
    for (int st = 128; st > 0; st >>= 1) {
        if (tid < st) dred[tid] += dred[tid + st];
        __syncthreads();
    }
    if (tid == 0) {
        double mean = dred[0] / ((double)NROWS * (double)NROWS);
        out[0] = (float)(-2.0 * mean);
        g_ctr2 = 0;   // reset for graph replay
    }
}

// ---------------------------------------------------------------------------
extern "C" void kernel_launch(void* const* d_in, const int* in_sizes, int n_in,
                              void* d_out, int out_size) {
    (void)in_sizes; (void)n_in; (void)out_size;
    const float* src = (const float*)d_in[0];
    const float* tgt = (const float*)d_in[1];
    float* out = (float*)d_out;

    cudaFuncSetAttribute(mmd_mma_kernel, cudaFuncAttributeMaxDynamicSharedMemorySize,
                         SMEM_TOT);

    stats_kernel<<<256, 256>>>(src, tgt);
    mmd_mma_kernel<<<dim3(32, 32), 256, SMEM_TOT>>>(out);
}

// round 6
// speedup vs baseline: 1.7439x; 1.1020x over previous
#include <cuda_runtime.h>
#include <cuda_bf16.h>
#include <stdint.h>

// ============================================================================
// MMD loss via mma.sync m16n8k16 bf16 (family-portable PTX; sm_103 base).
//   sum(L2) = 2*M*sum||x_i||^2 - 2*||sum x_i||^2  (M=8192)
//   bw = sum(L2)/(M^2-M)/4 ; e = exp(-L2/(16 bw))
//   kernel sum = e + e^2 + e^4 + e^8 + e^16 ; loss = -2*mean(cross block)
// R6: single __syncthreads per k-chunk (cutlass multistage order), 4-stage
// cp.async pipeline, hierarchical colsum reduction in stats.
// ============================================================================

#define NROWS 4096
#define D     256
#define M_TOT 8192

__device__ float    g_sq[M_TOT];
__device__ float    g_colsum_part[256][256];
__device__ float    g_colsum_l2[16][256];
__device__ float    g_inv_b16;
__device__ float    g_part[1024];
__device__ int      g_ctr_grp[16];
__device__ int      g_ctr1;
__device__ int      g_ctr2;
// bf16x2 fragment-major operands: [tile(256)][tk16(16)][lane(32)][4 regs]
__device__ uint32_t g_Aperm[NROWS * D / 2];
__device__ uint32_t g_Bperm[NROWS * D / 2];

// ---------------------------------------------------------------------------
__device__ __forceinline__ uint32_t smem_u32(const void* p) {
    uint32_t a;
    asm("{ .reg .u64 t; cvta.to.shared.u64 t, %1; cvt.u32.u64 %0, t; }"
        : "=r"(a) : "l"(p));
    return a;
}
__device__ __forceinline__ void cp_async16(uint32_t s, const void* g) {
    asm volatile("cp.async.cg.shared.global [%0], [%1], 16;"
                 :: "r"(s), "l"(g) : "memory");
}
#define CP_COMMIT() asm volatile("cp.async.commit_group;" ::: "memory")
#define CP_WAIT(n)  asm volatile("cp.async.wait_group %0;" :: "n"(n) : "memory")

__device__ __forceinline__ uint32_t pack_bf16x2(float lo, float hi) {
    uint32_t r;
    asm("cvt.rn.bf16x2.f32 %0, %1, %2;" : "=r"(r) : "f"(hi), "f"(lo));
    return r;
}

__device__ __forceinline__ void mma_bf16(float* c, uint32_t a0, uint32_t a1,
                                         uint32_t a2, uint32_t a3,
                                         uint32_t b0, uint32_t b1) {
    asm volatile(
        "mma.sync.aligned.m16n8k16.row.col.f32.bf16.bf16.f32 "
        "{%0,%1,%2,%3}, {%4,%5,%6,%7}, {%8,%9}, {%0,%1,%2,%3};"
        : "+f"(c[0]), "+f"(c[1]), "+f"(c[2]), "+f"(c[3])
        : "r"(a0), "r"(a1), "r"(a2), "r"(a3), "r"(b0), "r"(b1));
}

// ---------------------------------------------------------------------------
// Kernel 1: stats + bf16 fragment permute; hierarchical bandwidth reduction.
// 256 blocks x 256 threads; block handles 32 rows of [src; tgt].
// ---------------------------------------------------------------------------
__global__ __launch_bounds__(256) void stats_kernel(const float* __restrict__ src,
                                                    const float* __restrict__ tgt) {
    const int blk = blockIdx.x, tid = threadIdx.x;
    const int w = tid >> 5, lane = tid & 31;
    const bool isA = (blk < 128);
    const int base = isA ? blk * 32 : (blk - 128) * 32;
    const float* sbase = (isA ? src : tgt) + (size_t)base * D;

    __shared__ float tile[32][260];

    #pragma unroll
    for (int i = tid; i < 2048; i += 256) {
        const int r = i >> 6, c4 = (i & 63) * 4;
        float4 v = *(const float4*)(sbase + (size_t)r * D + c4);
        tile[r][c4] = v.x; tile[r][c4 + 1] = v.y;
        tile[r][c4 + 2] = v.z; tile[r][c4 + 3] = v.w;
    }
    __syncthreads();

    // column-sum partial
    float cs = 0.f;
    #pragma unroll 8
    for (int r = 0; r < 32; r++) cs += tile[r][tid];
    g_colsum_part[blk][tid] = cs;

    // row norms (warp w: rows 4w..4w+3)
    #pragma unroll
    for (int rr = 0; rr < 4; rr++) {
        const int r = w * 4 + rr;
        float sq = 0.f;
        #pragma unroll
        for (int j = 0; j < 8; j++) {
            const float x = tile[r][lane + 32 * j];
            sq += x * x;
        }
        #pragma unroll
        for (int off = 16; off > 0; off >>= 1) sq += __shfl_xor_sync(0xffffffffu, sq, off);
        if (lane == 0) g_sq[(isA ? base : NROWS + base) + r] = sq;
    }

    // bf16 fragment permute
    const int tile0 = (isA ? blk : blk - 128) * 2;
    uint4* dst = (uint4*)(isA ? g_Aperm : g_Bperm);
    #pragma unroll
    for (int i = tid; i < 1024; i += 256) {
        const int sub = i >> 9, tk = (i >> 5) & 15, l = i & 31;
        const int g = l >> 2, t = l & 3;
        const int r0 = sub * 16 + g, r1 = r0 + 8, c = tk * 16 + 2 * t;
        uint4 v;
        if (isA) {
            v.x = pack_bf16x2(tile[r0][c],     tile[r0][c + 1]);
            v.y = pack_bf16x2(tile[r1][c],     tile[r1][c + 1]);
            v.z = pack_bf16x2(tile[r0][c + 8], tile[r0][c + 9]);
            v.w = pack_bf16x2(tile[r1][c + 8], tile[r1][c + 9]);
        } else {
            v.x = pack_bf16x2(tile[r0][c],     tile[r0][c + 1]);
            v.y = pack_bf16x2(tile[r0][c + 8], tile[r0][c + 9]);
            v.z = pack_bf16x2(tile[r1][c],     tile[r1][c + 1]);
            v.w = pack_bf16x2(tile[r1][c + 8], tile[r1][c + 9]);
        }
        dst[(size_t)(tile0 + sub) * 512 + (tk * 32 + l)] = v;
    }

    // level-1: last block of each 16-block group reduces its group's partials
    __shared__ int flag1;
    __threadfence();
    if (tid == 0) flag1 = (atomicAdd(&g_ctr_grp[blk >> 4], 1) == 15);
    __syncthreads();
    if (!flag1) return;

    const int grp = blk >> 4;
    float gs = 0.f;
    #pragma unroll
    for (int p = 0; p < 16; p++) gs += g_colsum_part[grp * 16 + p][tid];
    g_colsum_l2[grp][tid] = gs;

    // level-2: last group reducer finishes bandwidth
    __shared__ int flag2;
    __threadfence();
    if (tid == 0) flag2 = (atomicAdd(&g_ctr1, 1) == 15);
    __syncthreads();
    if (!flag2) return;

    float csum = 0.f;
    #pragma unroll
    for (int p = 0; p < 16; p++) csum += g_colsum_l2[p][tid];
    double ssq = (double)csum * (double)csum;
    double sumsq = 0.0;
    #pragma unroll 8
    for (int m = 0; m < M_TOT / 256; m++) sumsq += (double)g_sq[tid + m * 256];

    __shared__ double r1s[256], r2s[256];
    r1s[tid] = ssq; r2s[tid] = sumsq;
    __syncthreads();
    for (int st = 128; st > 0; st >>= 1) {
        if (tid < st) { r1s[tid] += r1s[tid + st]; r2s[tid] += r2s[tid + st]; }
        __syncthreads();
    }
    if (tid == 0) {
        const double M = (double)M_TOT;
        double sumL2 = 2.0 * M * r2s[0] - 2.0 * r1s[0];
        double bw = sumL2 / (M * M - M) / 4.0;
        g_inv_b16 = (float)(1.0 / (bw * 16.0));
        g_ctr1 = 0;
    }
    if (tid < 16) g_ctr_grp[tid] = 0;   // reset for graph replay
}

// ---------------------------------------------------------------------------
// Kernel 2: bf16 mma GEMM + fused exp epilogue. 1024 CTAs x 256 threads.
// CTA 128x128, warp 32x64 (8 warps), k-chunks of 32, 4-stage cp.async,
// single __syncthreads per chunk.
// ---------------------------------------------------------------------------
#define OPND_BYTES 8192
#define BUF_BYTES  16384
#define NSTAGE     4
#define SMEM_TJ    (NSTAGE * BUF_BYTES)       // 65536
#define SMEM_RED   (SMEM_TJ + 512)
#define SMEM_TOT   (SMEM_RED + 64)

__global__ __launch_bounds__(256, 2)
void mmd_mma_kernel(float* __restrict__ out) {
    extern __shared__ char smem[];
    const uint32_t sb = smem_u32(smem);
    const int tid = threadIdx.x, wid = tid >> 5, lane = tid & 31;
    const int g = lane >> 2, t = lane & 3;
    const int warp_m = wid & 3, warp_n = wid >> 2;
    const int bx = blockIdx.x, by = blockIdx.y;

    float* tjs = (float*)(smem + SMEM_TJ);
    if (tid < 128) tjs[tid] = g_sq[NROWS + bx * 128 + tid];

    float acc[2][8][4];
    #pragma unroll
    for (int i = 0; i < 2; i++)
        #pragma unroll
        for (int j = 0; j < 8; j++)
            #pragma unroll
            for (int k = 0; k < 4; k++) acc[i][j][k] = 0.f;

    auto stage = [&](int kc, int buf) {
        const uint32_t sbuf = sb + buf * BUF_BYTES;
        #pragma unroll
        for (int v = 0; v < 2; v++) {
            const int soff = v * 4096 + tid * 16;
            const int seg = soff >> 9, within = soff & 511;
            const size_t ga = (((size_t)(by * 8 + (seg >> 1)) * 16 + kc * 2 + (seg & 1)) << 9) + within;
            cp_async16(sbuf + soff, (const char*)g_Aperm + ga);
            const size_t gb = (((size_t)(bx * 8 + (seg >> 1)) * 16 + kc * 2 + (seg & 1)) << 9) + within;
            cp_async16(sbuf + OPND_BYTES + soff, (const char*)g_Bperm + gb);
        }
    };

    stage(0, 0); CP_COMMIT();
    stage(1, 1); CP_COMMIT();
    stage(2, 2); CP_COMMIT();

    #pragma unroll
    for (int kc = 0; kc < 8; kc++) {
        // retire group kc, then ONE barrier: completed writes visible to all,
        // and all warps are past compute(kc-1) so stage(kc+3) may overwrite
        // buffer (kc+3)%4 == (kc-1)%4.
        if (kc < 6)       CP_WAIT(2);
        else if (kc == 6) CP_WAIT(1);
        else              CP_WAIT(0);
        __syncthreads();
        if (kc < 5) { stage(kc + 3, (kc + 3) & 3); CP_COMMIT(); }

        const uint4* As = (const uint4*)(smem + (kc & 3) * BUF_BYTES);
        const uint4* Bs = (const uint4*)(smem + (kc & 3) * BUF_BYTES + OPND_BYTES);

        #pragma unroll
        for (int ks = 0; ks < 2; ks++) {
            uint4 a[2], b[4];
            #pragma unroll
            for (int mt = 0; mt < 2; mt++)
                a[mt] = As[((warp_m * 2 + mt) * 2 + ks) * 32 + lane];
            #pragma unroll
            for (int pp = 0; pp < 4; pp++)
                b[pp] = Bs[((warp_n * 4 + pp) * 2 + ks) * 32 + lane];
            #pragma unroll
            for (int mt = 0; mt < 2; mt++)
                #pragma unroll
                for (int pp = 0; pp < 4; pp++) {
                    mma_bf16(acc[mt][2 * pp],     a[mt].x, a[mt].y, a[mt].z, a[mt].w, b[pp].x, b[pp].y);
                    mma_bf16(acc[mt][2 * pp + 1], a[mt].x, a[mt].y, a[mt].z, a[mt].w, b[pp].z, b[pp].w);
                }
        }
    }

    // epilogue: L2 -> 5-kernel exp sum
    const float inv_b16 = g_inv_b16;
    float si[2][2];
    #pragma unroll
    for (int mt = 0; mt < 2; mt++) {
        const int r0 = by * 128 + warp_m * 32 + mt * 16 + g;
        si[mt][0] = g_sq[r0];
        si[mt][1] = g_sq[r0 + 8];
    }

    float ksum = 0.f;
    #pragma unroll
    for (int nt = 0; nt < 8; nt++) {
        const int c0 = warp_n * 64 + nt * 8 + 2 * t;
        const float tj0 = tjs[c0], tj1 = tjs[c0 + 1];
        #pragma unroll
        for (int mt = 0; mt < 2; mt++) {
            const float* c = acc[mt][nt];
            #pragma unroll
            for (int q = 0; q < 4; q++) {
                const float L2 = si[mt][q >> 1] + ((q & 1) ? tj1 : tj0) - 2.f * c[q];
                const float e = __expf(-L2 * inv_b16);
                const float e2 = e * e, e4 = e2 * e2, e8 = e4 * e4;
                ksum += e + e2 + e4 + e8 + e8 * e8;
            }
        }
    }

    #pragma unroll
    for (int off = 16; off > 0; off >>= 1) ksum += __shfl_xor_sync(0xffffffffu, ksum, off);
    float* red = (float*)(smem + SMEM_RED);
    if (lane == 0) red[wid] = ksum;
    __syncthreads();
    if (tid == 0) {
        float bsum = 0.f;
        #pragma unroll
        for (int i = 0; i < 8; i++) bsum += red[i];
        g_part[by * 32 + bx] = bsum;
    }

    // last-CTA tail: final loss
    __shared__ int is_last;
    __threadfence();
    if (tid == 0) is_last = (atomicAdd(&g_ctr2, 1) == 1023);
    __syncthreads();
    if (!is_last) return;
    __threadfence();

    double sacc = 0.0;
    #pragma unroll
    for (int m = 0; m < 4; m++) sacc += (double)g_part[tid + m * 256];
    __shared__ double dred[256];
    dred[tid] = sacc;
    __syncthreads();
    for (int st = 128; st > 0; st >>= 1) {
        if (tid < st) dred[tid] += dred[tid + st];
        __syncthreads();
    }
    if (tid == 0) {
        double mean = dred[0] / ((double)NROWS * (double)NROWS);
        out[0] = (float)(-2.0 * mean);
        g_ctr2 = 0;
    }
}

// ---------------------------------------------------------------------------
extern "C" void kernel_launch(void* const* d_in, const int* in_sizes, int n_in,
                              void* d_out, int out_size) {
    (void)in_sizes; (void)n_in; (void)out_size;
    const float* src = (const float*)d_in[0];
    const float* tgt = (const float*)d_in[1];
    float* out = (float*)d_out;

    cudaFuncSetAttribute(mmd_mma_kernel, cudaFuncAttributeMaxDynamicSharedMemorySize,
                         SMEM_TOT);

    stats_kernel<<<256, 256>>>(src, tgt);
    mmd_mma_kernel<<<dim3(32, 32), 256, SMEM_TOT>>>(out);
}